// round 5
// baseline (speedup 1.0000x reference)
#include <cuda_runtime.h>
#include <cstdint>

#define T_LEN 6000
#define BATCH 64
#define HID   128
#define PROJ  32
#define G4    512
#define NTILE 750          // 6000 / 8

typedef unsigned long long u64;

// ---------------- f32x2 helpers ----------------
__device__ __forceinline__ u64 pk(float lo, float hi) {
    u64 r;
    asm("mov.b64 %0, {%1, %2};" : "=l"(r) : "f"(lo), "f"(hi));
    return r;
}
__device__ __forceinline__ void upk(u64 a, float& lo, float& hi) {
    asm("mov.b64 {%0, %1}, %2;" : "=f"(lo), "=f"(hi) : "l"(a));
}
__device__ __forceinline__ void fma2(u64& d, u64 a, u64 b) {
    asm("fma.rn.f32x2 %0, %1, %2, %3;" : "=l"(d) : "l"(a), "l"(b), "l"(d));
}
__device__ __forceinline__ u64 add2(u64 a, u64 b) {
    u64 r;
    asm("add.rn.f32x2 %0, %1, %2;" : "=l"(r) : "l"(a), "l"(b));
    return r;
}
__device__ __forceinline__ float hsum(u64 a) {
    float lo, hi; upk(a, lo, hi); return lo + hi;
}

// ---------------- activations ----------------
__device__ __forceinline__ float tanh_hw(float x) {          // MUFU.TANH
    float r; asm("tanh.approx.f32 %0, %1;" : "=f"(r) : "f"(x)); return r;
}
__device__ __forceinline__ float sigm(float x) {
    return fmaf(tanh_hw(x * 0.5f), 0.5f, 0.5f);
}
__device__ __forceinline__ float ex2_(float x) {
    float r; asm("ex2.approx.f32 %0, %1;" : "=f"(r) : "f"(x)); return r;
}
__device__ __forceinline__ float rcp_(float x) {
    float r; asm("rcp.approx.f32 %0, %1;" : "=f"(r) : "f"(x)); return r;
}
__device__ __forceinline__ float sigm_acc(float x) {         // final output sigmoid
    return rcp_(1.f + ex2_(-x * 1.4426950408889634f));
}

// ---------------- shared state (~107 KB dynamic) ----------------
struct SSmem {
    u64   x2buf[2][80][4];     // x (t,t+1) pairs for one 8-step tile, double buffered
    float xi0ring[2][8][512];  // xi0 tiles: [tile&1][t&7][gate]
    float xi1ring[16][512];    // [t&15][gate]
    float h0ring[16][32];      // [t&15][proj]
    float ot0s[128], ot1s[128];
    float hp0[2][4][32];       // step-parity double buffered partials
    float hp1[2][4][32];
    float hb0[4][32];          // warp-private h copies
    float hb1[4][32];
    u64   whr0s[4][16][32];    // [warp][pair][lane]
    u64   whr1s[4][16][32];
};

// ---------------- fused kernel: xi0-gen + layer0 + xi1-gemv + layer1 + head ----
// 384 threads, one block per batch element.
//   seg0 (warps 0-3):  per-window burst: produce next xi0 tile + 8 xi1 gemvs
//   seg1 (warps 4-7):  layer-1 cells + head (lag 16)
//   seg2 (warps 8-11): layer-0 cells (lag 0)   [highest wid = highest priority]
__global__ void __launch_bounds__(384, 1) fused_all(
    const float* __restrict__ x,
    const float* __restrict__ Wih0, const float* __restrict__ Whh0,
    const float* __restrict__ bih0, const float* __restrict__ bhh0,
    const float* __restrict__ Whr0,
    const float* __restrict__ Wih1, const float* __restrict__ Whh1,
    const float* __restrict__ bih1, const float* __restrict__ bhh1,
    const float* __restrict__ Whr1,
    const float* __restrict__ W2,   const float* __restrict__ b2,
    float* __restrict__ out)
{
    extern __shared__ __align__(16) char smem_raw[];
    SSmem& S = *reinterpret_cast<SSmem*>(smem_raw);

    const int b   = blockIdx.x;
    const int tid = threadIdx.x;
    const int seg = tid >> 7;          // 0: producer, 1: layer1, 2: layer0
    const int u   = tid & 127;
    const int w   = u >> 5, l = u & 31;

    u64   wgt[4][16];      // Whh0 (seg2) / Wih1 (seg0) / Whh1 (seg1)
    float bias1q[4];       // seg0: xi1 biases
    float bias0r[4];       // seg0: xi0 biases for its 4 gate rows
    u64   xr[3];           // seg0: prefetched x pairs
    float c = 0.f;
    float w2v = 0.f, b2v = 0.f;

    if (seg == 2) {                         // layer-0 cells
#pragma unroll
        for (int q = 0; q < 4; q++) {
            const u64* p = reinterpret_cast<const u64*>(Whh0 + (q * HID + u) * PROJ);
#pragma unroll
            for (int j = 0; j < 16; j++) wgt[q][j] = p[j];
        }
        const u64* wr = reinterpret_cast<const u64*>(Whr0 + l * HID + w * 32);
#pragma unroll
        for (int i = 0; i < 16; i++) S.whr0s[w][i][l] = wr[i];
        S.hb0[w][l] = 0.f;
    } else if (seg == 1) {                  // layer-1 cells + head
#pragma unroll
        for (int q = 0; q < 4; q++) {
            const u64* p = reinterpret_cast<const u64*>(Whh1 + (q * HID + u) * PROJ);
#pragma unroll
            for (int j = 0; j < 16; j++) wgt[q][j] = p[j];
        }
        const u64* wr = reinterpret_cast<const u64*>(Whr1 + l * HID + w * 32);
#pragma unroll
        for (int i = 0; i < 16; i++) S.whr1s[w][i][l] = wr[i];
        S.hb1[w][l] = 0.f;
        w2v = W2[l];
        b2v = b2[0];
    } else {                                // producer
#pragma unroll
        for (int q = 0; q < 4; q++) {
            const u64* p = reinterpret_cast<const u64*>(Wih1 + (q * HID + u) * PROJ);
#pragma unroll
            for (int j = 0; j < 16; j++) wgt[q][j] = p[j];
            bias1q[q] = bih1[q * HID + u] + bhh1[q * HID + u];
            bias0r[q] = bih0[q * HID + u] + bhh0[q * HID + u];
        }
    }

    // ---- seg0 prologue: produce xi0 tile 0, prefetch x tile 1 ----
    if (seg == 0) {
        // load + stage x tile 0
#pragma unroll
        for (int k = 0; k < 3; k++) {
            int idx = u + k * 128;
            if (idx < 320) {
                int f = idx >> 2, p = idx & 3;
                xr[k] = *reinterpret_cast<const u64*>(
                    x + (size_t)(b * 80 + f) * T_LEN + 2 * p);
            }
        }
#pragma unroll
        for (int k = 0; k < 3; k++) {
            int idx = u + k * 128;
            if (idx < 320) { int f = idx >> 2, p = idx & 3; S.x2buf[0][f][p] = xr[k]; }
        }
        asm volatile("bar.sync 3, 128;" ::: "memory");
        // produce tile 0 into xi0ring slot 0
        {
            const int xs = 0, slot = 0;
            u64 acc[4][4];
#pragma unroll
            for (int r = 0; r < 4; r++)
#pragma unroll
                for (int p = 0; p < 4; p++) acc[r][p] = pk(bias0r[r], bias0r[r]);
#pragma unroll 2
            for (int f4 = 0; f4 < 20; f4++) {
                u64 xv[4][4];
#pragma unroll
                for (int ff = 0; ff < 4; ff++) {
                    uint32_t sa = (uint32_t)__cvta_generic_to_shared(&S.x2buf[xs][f4*4+ff][0]);
                    asm("ld.shared.v2.u64 {%0, %1}, [%2];"    : "=l"(xv[ff][0]), "=l"(xv[ff][1]) : "r"(sa));
                    asm("ld.shared.v2.u64 {%0, %1}, [%2+16];" : "=l"(xv[ff][2]), "=l"(xv[ff][3]) : "r"(sa));
                }
#pragma unroll
                for (int r = 0; r < 4; r++) {
                    float4 wv = *reinterpret_cast<const float4*>(Wih0 + (r * HID + u) * 80 + f4 * 4);
                    u64 w0 = pk(wv.x, wv.x), w1 = pk(wv.y, wv.y);
                    u64 w2 = pk(wv.z, wv.z), w3 = pk(wv.w, wv.w);
#pragma unroll
                    for (int p = 0; p < 4; p++) {
                        fma2(acc[r][p], w0, xv[0][p]); fma2(acc[r][p], w1, xv[1][p]);
                        fma2(acc[r][p], w2, xv[2][p]); fma2(acc[r][p], w3, xv[3][p]);
                    }
                }
            }
#pragma unroll
            for (int r = 0; r < 4; r++)
#pragma unroll
                for (int p = 0; p < 4; p++) {
                    float lo, hi; upk(acc[r][p], lo, hi);
                    S.xi0ring[slot][2*p][r * HID + u]     = lo;
                    S.xi0ring[slot][2*p + 1][r * HID + u] = hi;
                }
        }
        // prefetch x tile 1
#pragma unroll
        for (int k = 0; k < 3; k++) {
            int idx = u + k * 128;
            if (idx < 320) {
                int f = idx >> 2, p = idx & 3;
                xr[k] = *reinterpret_cast<const u64*>(
                    x + (size_t)(b * 80 + f) * T_LEN + 8 + 2 * p);
            }
        }
    }
    __syncthreads();

    const int ITERS = T_LEN + 16;   // 6016, multiple of 8

    for (int i = 0; i < ITERS; i++) {
        if (seg == 2) {
            // ---------- layer-0 cell, step i ----------
            if (i < T_LEN) {
                const float* xq = S.xi0ring[(i >> 3) & 1][i & 7];
                float g0 = xq[u],           g1 = xq[HID + u];
                float g2 = xq[2*HID + u],   g3 = xq[3*HID + u];
                const u64* h2 = reinterpret_cast<const u64*>(S.hb0[w]);
                u64 aA0 = pk(0.f,0.f), aA1 = aA0, aA2 = aA0, aA3 = aA0;
                u64 aB0 = aA0, aB1 = aA0, aB2 = aA0, aB3 = aA0;
#pragma unroll
                for (int j = 0; j < 8; j++) {
                    u64 hv = h2[j];
                    fma2(aA0, wgt[0][j], hv); fma2(aA1, wgt[1][j], hv);
                    fma2(aA2, wgt[2][j], hv); fma2(aA3, wgt[3][j], hv);
                }
#pragma unroll
                for (int j = 8; j < 16; j++) {
                    u64 hv = h2[j];
                    fma2(aB0, wgt[0][j], hv); fma2(aB1, wgt[1][j], hv);
                    fma2(aB2, wgt[2][j], hv); fma2(aB3, wgt[3][j], hv);
                }
                g0 += hsum(add2(aA0, aB0));
                g1 += hsum(add2(aA1, aB1));
                g2 += hsum(add2(aA2, aB2));
                g3 += hsum(add2(aA3, aB3));

                float iv = sigm(g0), fv = sigm(g1);
                float gv = tanh_hw(g2), ov = sigm(g3);
                c = fmaf(fv, c, iv * gv);
                float ot = ov * tanh_hw(c);

                S.ot0s[u] = ot;
                __syncwarp();                    // own-warp slice only
                const u64* o2 = reinterpret_cast<const u64*>(S.ot0s) + w * 16;
                u64 pA = pk(0.f,0.f), pB = pA;
#pragma unroll
                for (int j = 0; j < 8; j++)  fma2(pA, S.whr0s[w][j][l], o2[j]);
#pragma unroll
                for (int j = 8; j < 16; j++) fma2(pB, S.whr0s[w][j][l], o2[j]);
                float* hp = S.hp0[i & 1][w];
                hp[l] = hsum(add2(pA, pB));
                asm volatile("bar.sync 1, 128;" ::: "memory");
                const float (*hpv)[32] = S.hp0[i & 1];
                float hv = (hpv[0][l] + hpv[1][l]) + (hpv[2][l] + hpv[3][l]);
                S.hb0[w][l] = hv;
                if (w == 0) S.h0ring[i & 15][l] = hv;
                __syncwarp();
            }
        } else if (seg == 1) {
            // ---------- layer-1 cell + head, step t = i-16 ----------
            const int t = i - 16;
            if (t >= 0) {
                const float* xq = S.xi1ring[t & 15];
                float g0 = xq[u],           g1 = xq[HID + u];
                float g2 = xq[2*HID + u],   g3 = xq[3*HID + u];
                const u64* h2 = reinterpret_cast<const u64*>(S.hb1[w]);
                u64 aA0 = pk(0.f,0.f), aA1 = aA0, aA2 = aA0, aA3 = aA0;
                u64 aB0 = aA0, aB1 = aA0, aB2 = aA0, aB3 = aA0;
#pragma unroll
                for (int j = 0; j < 8; j++) {
                    u64 hv = h2[j];
                    fma2(aA0, wgt[0][j], hv); fma2(aA1, wgt[1][j], hv);
                    fma2(aA2, wgt[2][j], hv); fma2(aA3, wgt[3][j], hv);
                }
#pragma unroll
                for (int j = 8; j < 16; j++) {
                    u64 hv = h2[j];
                    fma2(aB0, wgt[0][j], hv); fma2(aB1, wgt[1][j], hv);
                    fma2(aB2, wgt[2][j], hv); fma2(aB3, wgt[3][j], hv);
                }
                g0 += hsum(add2(aA0, aB0));
                g1 += hsum(add2(aA1, aB1));
                g2 += hsum(add2(aA2, aB2));
                g3 += hsum(add2(aA3, aB3));

                float iv = sigm(g0), fv = sigm(g1);
                float gv = tanh_hw(g2), ov = sigm(g3);
                c = fmaf(fv, c, iv * gv);
                float ot = ov * tanh_hw(c);

                S.ot1s[u] = ot;
                __syncwarp();
                const u64* o2 = reinterpret_cast<const u64*>(S.ot1s) + w * 16;
                u64 pA = pk(0.f,0.f), pB = pA;
#pragma unroll
                for (int j = 0; j < 8; j++)  fma2(pA, S.whr1s[w][j][l], o2[j]);
#pragma unroll
                for (int j = 8; j < 16; j++) fma2(pB, S.whr1s[w][j][l], o2[j]);
                float* hp = S.hp1[i & 1][w];
                hp[l] = hsum(add2(pA, pB));
                asm volatile("bar.sync 2, 128;" ::: "memory");
                const float (*hpv)[32] = S.hp1[i & 1];
                float hv = (hpv[0][l] + hpv[1][l]) + (hpv[2][l] + hpv[3][l]);
                S.hb1[w][l] = hv;
                if (w == 0) {
                    float val = fmaxf(hv, 0.f) * w2v;
#pragma unroll
                    for (int off = 16; off; off >>= 1)
                        val += __shfl_down_sync(0xffffffffu, val, off);
                    if (l == 0) {
                        float z = fmaxf(val + b2v, 0.f);
                        out[(size_t)b * T_LEN + t] = sigm_acc(z);
                    }
                }
                __syncwarp();
            }
        } else {
            // ---------- producer: once per window ----------
            if ((i & 7) == 0) {
                const int w8    = i >> 3;
                const int ptile = w8 + 1;
                if (ptile < NTILE) {
                    const int xs = ptile & 1;
                    // stage prefetched x
#pragma unroll
                    for (int k = 0; k < 3; k++) {
                        int idx = u + k * 128;
                        if (idx < 320) { int f = idx >> 2, p = idx & 3; S.x2buf[xs][f][p] = xr[k]; }
                    }
                    asm volatile("bar.sync 3, 128;" ::: "memory");
                    // produce xi0 tile ptile
                    u64 acc[4][4];
#pragma unroll
                    for (int r = 0; r < 4; r++)
#pragma unroll
                        for (int p = 0; p < 4; p++) acc[r][p] = pk(bias0r[r], bias0r[r]);
#pragma unroll 2
                    for (int f4 = 0; f4 < 20; f4++) {
                        u64 xv[4][4];
#pragma unroll
                        for (int ff = 0; ff < 4; ff++) {
                            uint32_t sa = (uint32_t)__cvta_generic_to_shared(&S.x2buf[xs][f4*4+ff][0]);
                            asm("ld.shared.v2.u64 {%0, %1}, [%2];"    : "=l"(xv[ff][0]), "=l"(xv[ff][1]) : "r"(sa));
                            asm("ld.shared.v2.u64 {%0, %1}, [%2+16];" : "=l"(xv[ff][2]), "=l"(xv[ff][3]) : "r"(sa));
                        }
#pragma unroll
                        for (int r = 0; r < 4; r++) {
                            float4 wv = *reinterpret_cast<const float4*>(Wih0 + (r * HID + u) * 80 + f4 * 4);
                            u64 w0 = pk(wv.x, wv.x), w1 = pk(wv.y, wv.y);
                            u64 w2 = pk(wv.z, wv.z), w3 = pk(wv.w, wv.w);
#pragma unroll
                            for (int p = 0; p < 4; p++) {
                                fma2(acc[r][p], w0, xv[0][p]); fma2(acc[r][p], w1, xv[1][p]);
                                fma2(acc[r][p], w2, xv[2][p]); fma2(acc[r][p], w3, xv[3][p]);
                            }
                        }
                    }
#pragma unroll
                    for (int r = 0; r < 4; r++)
#pragma unroll
                        for (int p = 0; p < 4; p++) {
                            float lo, hi; upk(acc[r][p], lo, hi);
                            S.xi0ring[xs][2*p][r * HID + u]     = lo;
                            S.xi0ring[xs][2*p + 1][r * HID + u] = hi;
                        }
                    // prefetch x for ptile+1
                    const int ntile = ptile + 1;
                    if (ntile < NTILE) {
                        const size_t t0 = (size_t)ntile * 8;
#pragma unroll
                        for (int k = 0; k < 3; k++) {
                            int idx = u + k * 128;
                            if (idx < 320) {
                                int f = idx >> 2, p = idx & 3;
                                xr[k] = *reinterpret_cast<const u64*>(
                                    x + (size_t)(b * 80 + f) * T_LEN + t0 + 2 * p);
                            }
                        }
                    }
                }
                // xi1 gemvs for t in [i-8, i)
#pragma unroll 2
                for (int k = 0; k < 8; k++) {
                    const int t = i - 8 + k;
                    if ((unsigned)t < (unsigned)T_LEN) {
                        const u64* h2 = reinterpret_cast<const u64*>(S.h0ring[t & 15]);
                        u64 aA0 = pk(0.f,0.f), aA1 = aA0, aA2 = aA0, aA3 = aA0;
                        u64 aB0 = aA0, aB1 = aA0, aB2 = aA0, aB3 = aA0;
#pragma unroll
                        for (int j = 0; j < 8; j++) {
                            u64 hv = h2[j];
                            fma2(aA0, wgt[0][j], hv); fma2(aA1, wgt[1][j], hv);
                            fma2(aA2, wgt[2][j], hv); fma2(aA3, wgt[3][j], hv);
                        }
#pragma unroll
                        for (int j = 8; j < 16; j++) {
                            u64 hv = h2[j];
                            fma2(aB0, wgt[0][j], hv); fma2(aB1, wgt[1][j], hv);
                            fma2(aB2, wgt[2][j], hv); fma2(aB3, wgt[3][j], hv);
                        }
                        float* xo = S.xi1ring[t & 15];
                        xo[u]           = bias1q[0] + hsum(add2(aA0, aB0));
                        xo[HID + u]     = bias1q[1] + hsum(add2(aA1, aB1));
                        xo[2*HID + u]   = bias1q[2] + hsum(add2(aA2, aB2));
                        xo[3*HID + u]   = bias1q[3] + hsum(add2(aA3, aB3));
                    }
                }
            }
        }
        if ((i & 7) == 7) __syncthreads();   // window barrier
    }
}

// ---------------- launch ----------------
extern "C" void kernel_launch(void* const* d_in, const int* in_sizes, int n_in,
                              void* d_out, int out_size)
{
    const float* x    = (const float*)d_in[0];
    const float* Wih0 = (const float*)d_in[1];
    const float* Whh0 = (const float*)d_in[2];
    const float* bih0 = (const float*)d_in[3];
    const float* bhh0 = (const float*)d_in[4];
    const float* Whr0 = (const float*)d_in[5];
    const float* Wih1 = (const float*)d_in[6];
    const float* Whh1 = (const float*)d_in[7];
    const float* bih1 = (const float*)d_in[8];
    const float* bhh1 = (const float*)d_in[9];
    const float* Whr1 = (const float*)d_in[10];
    const float* W2   = (const float*)d_in[11];
    const float* b2   = (const float*)d_in[12];
    float* out = (float*)d_out;

    const int smemBytes = (int)sizeof(SSmem);
    static bool attrSet = false;
    if (!attrSet) {
        cudaFuncSetAttribute(fused_all,
                             cudaFuncAttributeMaxDynamicSharedMemorySize, smemBytes);
        attrSet = true;
    }

    fused_all<<<BATCH, 384, smemBytes>>>(x,
                                         Wih0, Whh0, bih0, bhh0, Whr0,
                                         Wih1, Whh1, bih1, bhh1, Whr1,
                                         W2, b2, out);
}

// round 6
// speedup vs baseline: 1.4299x; 1.4299x over previous
#include <cuda_runtime.h>
#include <cstdint>

#define T_LEN 6000
#define BATCH 64
#define HID   128
#define PROJ  32
#define G4    512

typedef unsigned long long u64;

// ---------------- scratch ----------------
__device__ float g_xi [(size_t)T_LEN * BATCH * G4];   // xi0 (from gemm0)
__device__ float g_xi1[(size_t)T_LEN * BATCH * G4];   // xi1 (L0 -> L1 handoff)
__device__ int   g_wm [BATCH];                        // per-batch xi1 watermark

// ---------------- f32x2 helpers ----------------
__device__ __forceinline__ u64 pk(float lo, float hi) {
    u64 r;
    asm("mov.b64 %0, {%1, %2};" : "=l"(r) : "f"(lo), "f"(hi));
    return r;
}
__device__ __forceinline__ void upk(u64 a, float& lo, float& hi) {
    asm("mov.b64 {%0, %1}, %2;" : "=f"(lo), "=f"(hi) : "l"(a));
}
__device__ __forceinline__ void fma2(u64& d, u64 a, u64 b) {
    asm("fma.rn.f32x2 %0, %1, %2, %3;" : "=l"(d) : "l"(a), "l"(b), "l"(d));
}
__device__ __forceinline__ u64 add2(u64 a, u64 b) {
    u64 r;
    asm("add.rn.f32x2 %0, %1, %2;" : "=l"(r) : "l"(a), "l"(b));
    return r;
}
__device__ __forceinline__ float hsum(u64 a) {
    float lo, hi; upk(a, lo, hi); return lo + hi;
}

// ---------------- activations ----------------
__device__ __forceinline__ float tanh_hw(float x) {
    float r; asm("tanh.approx.f32 %0, %1;" : "=f"(r) : "f"(x)); return r;
}
__device__ __forceinline__ float sigm(float x) {
    return fmaf(tanh_hw(x * 0.5f), 0.5f, 0.5f);
}
__device__ __forceinline__ float ex2_(float x) {
    float r; asm("ex2.approx.f32 %0, %1;" : "=f"(r) : "f"(x)); return r;
}
__device__ __forceinline__ float rcp_(float x) {
    float r; asm("rcp.approx.f32 %0, %1;" : "=f"(r) : "f"(x)); return r;
}
__device__ __forceinline__ float sigm_acc(float x) {
    return rcp_(1.f + ex2_(-x * 1.4426950408889634f));
}

// ---------------- flag ops ----------------
__device__ __forceinline__ void wm_store(int* p, int v) {
    asm volatile("st.release.gpu.global.s32 [%0], %1;" :: "l"(p), "r"(v) : "memory");
}
__device__ __forceinline__ int wm_load(const int* p) {
    int v;
    asm volatile("ld.acquire.gpu.global.s32 %0, [%1];" : "=r"(v) : "l"(p) : "memory");
    return v;
}

// ---------------- init: zero watermarks ----------------
__global__ void init_wm() {
    if (threadIdx.x < BATCH) g_wm[threadIdx.x] = 0;
}

// ---------------- GEMM0 (proven) ----------------
__global__ void __launch_bounds__(512, 1) gemm_xi0(
    const float* __restrict__ x, const float* __restrict__ Wih,
    const float* __restrict__ bih, const float* __restrict__ bhh,
    float* __restrict__ xi)
{
    int b  = blockIdx.y;
    int t0 = blockIdx.x * 128;
    int g  = threadIdx.x;

    __shared__ u64 xs2[80][64];

    for (int idx = g; idx < 80 * 32; idx += 512) {
        int f = idx >> 5, i4 = idx & 31;
        int t = t0 + i4 * 4;
        const float* src = x + ((size_t)b * 80 + f) * T_LEN + t;
        float4 v;
        if (t + 3 < T_LEN) {
            v = *reinterpret_cast<const float4*>(src);
        } else {
            v.x = (t     < T_LEN) ? src[0] : 0.f;
            v.y = (t + 1 < T_LEN) ? src[1] : 0.f;
            v.z = (t + 2 < T_LEN) ? src[2] : 0.f;
            v.w = (t + 3 < T_LEN) ? src[3] : 0.f;
        }
        xs2[f][i4 * 2]     = pk(v.x, v.y);
        xs2[f][i4 * 2 + 1] = pk(v.z, v.w);
    }

    float w[80];
#pragma unroll
    for (int f = 0; f < 80; f++) w[f] = Wih[g * 80 + f];
    float bias = bih[g] + bhh[g];
    __syncthreads();

    int tmax = min(128, T_LEN - t0);
    const size_t st = (size_t)BATCH * G4;

    for (int i8 = 0; i8 < tmax / 8; i8++) {
        u64 a0 = pk(bias, bias), a1 = a0, a2 = a0, a3 = a0;
#pragma unroll
        for (int f = 0; f < 80; f++) {
            u64 pA, pB, pC, pD;
            uint32_t sa = (uint32_t)__cvta_generic_to_shared(&xs2[f][i8 * 4]);
            asm("ld.shared.v2.u64 {%0, %1}, [%2];"    : "=l"(pA), "=l"(pB) : "r"(sa));
            asm("ld.shared.v2.u64 {%0, %1}, [%2+16];" : "=l"(pC), "=l"(pD) : "r"(sa));
            u64 w2 = pk(w[f], w[f]);
            fma2(a0, w2, pA); fma2(a1, w2, pB);
            fma2(a2, w2, pC); fma2(a3, w2, pD);
        }
        size_t o = ((size_t)(t0 + i8 * 8) * BATCH + b) * G4 + g;
        float lo, hi;
        upk(a0, lo, hi); xi[o]          = lo; xi[o + st]     = hi;
        upk(a1, lo, hi); xi[o + 2 * st] = lo; xi[o + 3 * st] = hi;
        upk(a2, lo, hi); xi[o + 4 * st] = lo; xi[o + 5 * st] = hi;
        upk(a3, lo, hi); xi[o + 6 * st] = lo; xi[o + 7 * st] = hi;
    }
}

// ---------------- split scan: 128 blocks ----------------
// blocks 0-63  (L0): layer-0 cells (warps 4-7) + xi1 gemv (warps 0-3) -> g_xi1 + wm
// blocks 64-127(L1): layer-1 cells + head (128 threads; warps 4-7 idle-exit)
__global__ void __launch_bounds__(256, 1) scan_kernel(
    const float* __restrict__ Whh0, const float* __restrict__ Whr0,
    const float* __restrict__ Wih1,
    const float* __restrict__ bih1, const float* __restrict__ bhh1,
    const float* __restrict__ Whh1, const float* __restrict__ Whr1,
    const float* __restrict__ W2,   const float* __restrict__ b2,
    float* __restrict__ out)
{
    __shared__ __align__(16) float ring[8][32];     // L0: h0 ring
    __shared__ __align__(16) float ots[128];
    __shared__ __align__(16) float hp[2][4][32];    // step-parity partials
    __shared__ __align__(16) float hb[4][32];       // warp-private h copies
    __shared__ u64 whrS[4][16][32];                 // [warp][pair][lane]

    const bool isL0 = blockIdx.x < 64;
    const int  b    = isL0 ? blockIdx.x : blockIdx.x - 64;
    const int  tid  = threadIdx.x;

    if (isL0) {
        // ================= L0 =================
        const int seg = tid >> 7;        // 0: xi1 gemv, 1: cells (higher wid = priority)
        const int u   = tid & 127;
        const int w   = u >> 5, l = u & 31;

        u64   wgt[4][16];
        float bias1q[4];
        float c = 0.f;

        if (seg == 1) {
#pragma unroll
            for (int q = 0; q < 4; q++) {
                const u64* p = reinterpret_cast<const u64*>(Whh0 + (q * HID + u) * PROJ);
#pragma unroll
                for (int j = 0; j < 16; j++) wgt[q][j] = p[j];
            }
            const u64* wr = reinterpret_cast<const u64*>(Whr0 + l * HID + w * 32);
#pragma unroll
            for (int i = 0; i < 16; i++) whrS[w][i][l] = wr[i];
            hb[w][l] = 0.f;
        } else {
#pragma unroll
            for (int q = 0; q < 4; q++) {
                const u64* p = reinterpret_cast<const u64*>(Wih1 + (q * HID + u) * PROJ);
#pragma unroll
                for (int j = 0; j < 16; j++) wgt[q][j] = p[j];
                bias1q[q] = bih1[q * HID + u] + bhh1[q * HID + u];
            }
        }
        __syncthreads();

        const size_t strideT = (size_t)BATCH * G4;
        const float* xp = g_xi + (size_t)b * G4 + u;
        float cur[4], nxt[4];
        if (seg == 1) {
#pragma unroll
            for (int q = 0; q < 4; q++) cur[q] = __ldcs(xp + q * HID);
#pragma unroll
            for (int q = 0; q < 4; q++) nxt[q] = __ldcs(xp + strideT + q * HID);
        }

        const int ITERS = T_LEN + 4;   // 6004, multiple of 4

        for (int i = 0; i < ITERS; i++) {
            if (seg == 1) {
                // ----- layer-0 cell, step i -----
                if (i < T_LEN) {
                    float g0 = cur[0], g1 = cur[1], g2 = cur[2], g3 = cur[3];
#pragma unroll
                    for (int q = 0; q < 4; q++) cur[q] = nxt[q];
                    if (i + 2 < T_LEN) {
                        const float* xn = xp + (size_t)(i + 2) * strideT;
#pragma unroll
                        for (int q = 0; q < 4; q++) nxt[q] = __ldcs(xn + q * HID);
                    }
                    const u64* h2 = reinterpret_cast<const u64*>(hb[w]);
                    u64 aA0 = pk(0.f,0.f), aA1 = aA0, aA2 = aA0, aA3 = aA0;
                    u64 aB0 = aA0, aB1 = aA0, aB2 = aA0, aB3 = aA0;
#pragma unroll
                    for (int j = 0; j < 8; j++) {
                        u64 hv = h2[j];
                        fma2(aA0, wgt[0][j], hv); fma2(aA1, wgt[1][j], hv);
                        fma2(aA2, wgt[2][j], hv); fma2(aA3, wgt[3][j], hv);
                    }
#pragma unroll
                    for (int j = 8; j < 16; j++) {
                        u64 hv = h2[j];
                        fma2(aB0, wgt[0][j], hv); fma2(aB1, wgt[1][j], hv);
                        fma2(aB2, wgt[2][j], hv); fma2(aB3, wgt[3][j], hv);
                    }
                    g0 += hsum(add2(aA0, aB0));
                    g1 += hsum(add2(aA1, aB1));
                    g2 += hsum(add2(aA2, aB2));
                    g3 += hsum(add2(aA3, aB3));

                    float iv = sigm(g0), fv = sigm(g1);
                    float gv = tanh_hw(g2), ov = sigm(g3);
                    c = fmaf(fv, c, iv * gv);
                    float ot = ov * tanh_hw(c);

                    ots[u] = ot;
                    __syncwarp();
                    const u64* o2 = reinterpret_cast<const u64*>(ots) + w * 16;
                    u64 pA = pk(0.f,0.f), pB = pA;
#pragma unroll
                    for (int j = 0; j < 8; j++)  fma2(pA, whrS[w][j][l], o2[j]);
#pragma unroll
                    for (int j = 8; j < 16; j++) fma2(pB, whrS[w][j][l], o2[j]);
                    hp[i & 1][w][l] = hsum(add2(pA, pB));
                    asm volatile("bar.sync 1, 128;" ::: "memory");
                    const float (*hpv)[32] = hp[i & 1];
                    float hv = (hpv[0][l] + hpv[1][l]) + (hpv[2][l] + hpv[3][l]);
                    hb[w][l] = hv;
                    if (w == 0) ring[i & 7][l] = hv;
                    __syncwarp();
                }
            } else {
                // ----- xi1 gemv, step t = i-4 -----
                const int t = i - 4;
                if (t >= 0 && t < T_LEN) {
                    const u64* h2 = reinterpret_cast<const u64*>(ring[t & 7]);
                    u64 aA0 = pk(0.f,0.f), aA1 = aA0, aA2 = aA0, aA3 = aA0;
                    u64 aB0 = aA0, aB1 = aA0, aB2 = aA0, aB3 = aA0;
#pragma unroll
                    for (int j = 0; j < 8; j++) {
                        u64 hv = h2[j];
                        fma2(aA0, wgt[0][j], hv); fma2(aA1, wgt[1][j], hv);
                        fma2(aA2, wgt[2][j], hv); fma2(aA3, wgt[3][j], hv);
                    }
#pragma unroll
                    for (int j = 8; j < 16; j++) {
                        u64 hv = h2[j];
                        fma2(aB0, wgt[0][j], hv); fma2(aB1, wgt[1][j], hv);
                        fma2(aB2, wgt[2][j], hv); fma2(aB3, wgt[3][j], hv);
                    }
                    float* xo = g_xi1 + ((size_t)t * BATCH + b) * G4;
                    xo[u]           = bias1q[0] + hsum(add2(aA0, aB0));
                    xo[HID + u]     = bias1q[1] + hsum(add2(aA1, aB1));
                    xo[2*HID + u]   = bias1q[2] + hsum(add2(aA2, aB2));
                    xo[3*HID + u]   = bias1q[3] + hsum(add2(aA3, aB3));
                }
            }
            if ((i & 3) == 3) {
                if (seg == 0 && i >= 4) __threadfence();   // publish xi1 stores
                __syncthreads();
                if (tid == 0 && i >= 7) {
                    int v = i - 3; if (v > T_LEN) v = T_LEN;
                    wm_store(&g_wm[b], v);                 // xi1 done through v-1
                }
            }
        }
        if (tid == 0) { __threadfence(); wm_store(&g_wm[b], T_LEN); }
    } else {
        // ================= L1 =================
        if (tid >= 128) return;     // lone 128-thread group; named barriers only
        const int u = tid;
        const int w = u >> 5, l = u & 31;

        u64 wgt[4][16];
#pragma unroll
        for (int q = 0; q < 4; q++) {
            const u64* p = reinterpret_cast<const u64*>(Whh1 + (q * HID + u) * PROJ);
#pragma unroll
            for (int j = 0; j < 16; j++) wgt[q][j] = p[j];
        }
        const u64* wr = reinterpret_cast<const u64*>(Whr1 + l * HID + w * 32);
#pragma unroll
        for (int i = 0; i < 16; i++) whrS[w][i][l] = wr[i];
        hb[w][l] = 0.f;
        float w2v = W2[l];
        float b2v = b2[0];
        float c = 0.f;
        asm volatile("bar.sync 1, 128;" ::: "memory");

        const size_t strideT = (size_t)BATCH * G4;
        const float* xp = g_xi1 + (size_t)b * G4 + u;

        // initial poll + 2-deep prefetch
        {
            int need = 10 < T_LEN ? 10 : T_LEN;
            while (wm_load(&g_wm[b]) < need) __nanosleep(200);
        }
        float cur[4], nxt[4];
#pragma unroll
        for (int q = 0; q < 4; q++) cur[q] = __ldcs(xp + q * HID);
#pragma unroll
        for (int q = 0; q < 4; q++) nxt[q] = __ldcs(xp + strideT + q * HID);

        for (int t = 0; t < T_LEN; t++) {
            if ((t & 7) == 0 && t) {
                int need = t + 10; if (need > T_LEN) need = T_LEN;
                while (wm_load(&g_wm[b]) < need) __nanosleep(200);
            }
            float g0 = cur[0], g1 = cur[1], g2 = cur[2], g3 = cur[3];
#pragma unroll
            for (int q = 0; q < 4; q++) cur[q] = nxt[q];
            if (t + 2 < T_LEN) {
                const float* xn = xp + (size_t)(t + 2) * strideT;
#pragma unroll
                for (int q = 0; q < 4; q++) nxt[q] = __ldcs(xn + q * HID);
            }
            const u64* h2 = reinterpret_cast<const u64*>(hb[w]);
            u64 aA0 = pk(0.f,0.f), aA1 = aA0, aA2 = aA0, aA3 = aA0;
            u64 aB0 = aA0, aB1 = aA0, aB2 = aA0, aB3 = aA0;
#pragma unroll
            for (int j = 0; j < 8; j++) {
                u64 hv = h2[j];
                fma2(aA0, wgt[0][j], hv); fma2(aA1, wgt[1][j], hv);
                fma2(aA2, wgt[2][j], hv); fma2(aA3, wgt[3][j], hv);
            }
#pragma unroll
            for (int j = 8; j < 16; j++) {
                u64 hv = h2[j];
                fma2(aB0, wgt[0][j], hv); fma2(aB1, wgt[1][j], hv);
                fma2(aB2, wgt[2][j], hv); fma2(aB3, wgt[3][j], hv);
            }
            g0 += hsum(add2(aA0, aB0));
            g1 += hsum(add2(aA1, aB1));
            g2 += hsum(add2(aA2, aB2));
            g3 += hsum(add2(aA3, aB3));

            float iv = sigm(g0), fv = sigm(g1);
            float gv = tanh_hw(g2), ov = sigm(g3);
            c = fmaf(fv, c, iv * gv);
            float ot = ov * tanh_hw(c);

            ots[u] = ot;
            __syncwarp();
            const u64* o2 = reinterpret_cast<const u64*>(ots) + w * 16;
            u64 pA = pk(0.f,0.f), pB = pA;
#pragma unroll
            for (int j = 0; j < 8; j++)  fma2(pA, whrS[w][j][l], o2[j]);
#pragma unroll
            for (int j = 8; j < 16; j++) fma2(pB, whrS[w][j][l], o2[j]);
            hp[t & 1][w][l] = hsum(add2(pA, pB));
            asm volatile("bar.sync 1, 128;" ::: "memory");
            const float (*hpv)[32] = hp[t & 1];
            float hv = (hpv[0][l] + hpv[1][l]) + (hpv[2][l] + hpv[3][l]);
            hb[w][l] = hv;
            if (w == 0) {
                float val = fmaxf(hv, 0.f) * w2v;
#pragma unroll
                for (int off = 16; off; off >>= 1)
                    val += __shfl_down_sync(0xffffffffu, val, off);
                if (l == 0) {
                    float z = fmaxf(val + b2v, 0.f);
                    out[(size_t)b * T_LEN + t] = sigm_acc(z);
                }
            }
            __syncwarp();
        }
    }
}

// ---------------- launch ----------------
extern "C" void kernel_launch(void* const* d_in, const int* in_sizes, int n_in,
                              void* d_out, int out_size)
{
    const float* x    = (const float*)d_in[0];
    const float* Wih0 = (const float*)d_in[1];
    const float* Whh0 = (const float*)d_in[2];
    const float* bih0 = (const float*)d_in[3];
    const float* bhh0 = (const float*)d_in[4];
    const float* Whr0 = (const float*)d_in[5];
    const float* Wih1 = (const float*)d_in[6];
    const float* Whh1 = (const float*)d_in[7];
    const float* bih1 = (const float*)d_in[8];
    const float* bhh1 = (const float*)d_in[9];
    const float* Whr1 = (const float*)d_in[10];
    const float* W2   = (const float*)d_in[11];
    const float* b2   = (const float*)d_in[12];
    float* out = (float*)d_out;

    float* xi;
    cudaGetSymbolAddress((void**)&xi, g_xi);

    dim3 gridG((T_LEN + 127) / 128, BATCH);

    init_wm<<<1, 64>>>();
    gemm_xi0<<<gridG, 512>>>(x, Wih0, bih0, bhh0, xi);
    scan_kernel<<<128, 256>>>(Whh0, Whr0,
                              Wih1, bih1, bhh1, Whh1, Whr1,
                              W2, b2, out);
}

// round 7
// speedup vs baseline: 1.8964x; 1.3263x over previous
#include <cuda_runtime.h>
#include <cstdint>

#define T_LEN 6000
#define BATCH 64
#define HID   128
#define PROJ  32
#define G4    512

typedef unsigned long long u64;

// ---------------- scratch ----------------
__device__ float g_xi [(size_t)T_LEN * BATCH * G4];    // xi0 (from gemm0)
__device__ float g_xi1[(size_t)T_LEN * BATCH * G4];    // xi1 (G -> C1)
__device__ float g_h0 [(size_t)T_LEN * BATCH * PROJ];  // h0  (C0 -> G)
__device__ int   g_wm0[BATCH];                         // h0 watermark
__device__ int   g_wm1[BATCH];                         // xi1 watermark

// ---------------- f32x2 helpers ----------------
__device__ __forceinline__ u64 pk(float lo, float hi) {
    u64 r;
    asm("mov.b64 %0, {%1, %2};" : "=l"(r) : "f"(lo), "f"(hi));
    return r;
}
__device__ __forceinline__ void upk(u64 a, float& lo, float& hi) {
    asm("mov.b64 {%0, %1}, %2;" : "=f"(lo), "=f"(hi) : "l"(a));
}
__device__ __forceinline__ void fma2(u64& d, u64 a, u64 b) {
    asm("fma.rn.f32x2 %0, %1, %2, %3;" : "=l"(d) : "l"(a), "l"(b), "l"(d));
}
__device__ __forceinline__ u64 add2(u64 a, u64 b) {
    u64 r;
    asm("add.rn.f32x2 %0, %1, %2;" : "=l"(r) : "l"(a), "l"(b));
    return r;
}
__device__ __forceinline__ float hsum(u64 a) {
    float lo, hi; upk(a, lo, hi); return lo + hi;
}

// ---------------- activations ----------------
__device__ __forceinline__ float tanh_hw(float x) {
    float r; asm("tanh.approx.f32 %0, %1;" : "=f"(r) : "f"(x)); return r;
}
__device__ __forceinline__ float sigm(float x) {
    return fmaf(tanh_hw(x * 0.5f), 0.5f, 0.5f);
}
__device__ __forceinline__ float ex2_(float x) {
    float r; asm("ex2.approx.f32 %0, %1;" : "=f"(r) : "f"(x)); return r;
}
__device__ __forceinline__ float rcp_(float x) {
    float r; asm("rcp.approx.f32 %0, %1;" : "=f"(r) : "f"(x)); return r;
}
__device__ __forceinline__ float sigm_acc(float x) {
    return rcp_(1.f + ex2_(-x * 1.4426950408889634f));
}

// ---------------- flag ops ----------------
__device__ __forceinline__ void wm_store(int* p, int v) {
    asm volatile("st.release.gpu.global.s32 [%0], %1;" :: "l"(p), "r"(v) : "memory");
}
__device__ __forceinline__ int wm_load(const int* p) {
    int v;
    asm volatile("ld.acquire.gpu.global.s32 %0, [%1];" : "=r"(v) : "l"(p) : "memory");
    return v;
}

__global__ void init_wm() {
    if (threadIdx.x < BATCH) { g_wm0[threadIdx.x] = 0; g_wm1[threadIdx.x] = 0; }
}

// ---------------- GEMM0 (proven) ----------------
__global__ void __launch_bounds__(512, 1) gemm_xi0(
    const float* __restrict__ x, const float* __restrict__ Wih,
    const float* __restrict__ bih, const float* __restrict__ bhh,
    float* __restrict__ xi)
{
    int b  = blockIdx.y;
    int t0 = blockIdx.x * 128;
    int g  = threadIdx.x;

    __shared__ u64 xs2[80][64];

    for (int idx = g; idx < 80 * 32; idx += 512) {
        int f = idx >> 5, i4 = idx & 31;
        int t = t0 + i4 * 4;
        const float* src = x + ((size_t)b * 80 + f) * T_LEN + t;
        float4 v;
        if (t + 3 < T_LEN) {
            v = *reinterpret_cast<const float4*>(src);
        } else {
            v.x = (t     < T_LEN) ? src[0] : 0.f;
            v.y = (t + 1 < T_LEN) ? src[1] : 0.f;
            v.z = (t + 2 < T_LEN) ? src[2] : 0.f;
            v.w = (t + 3 < T_LEN) ? src[3] : 0.f;
        }
        xs2[f][i4 * 2]     = pk(v.x, v.y);
        xs2[f][i4 * 2 + 1] = pk(v.z, v.w);
    }

    float w[80];
#pragma unroll
    for (int f = 0; f < 80; f++) w[f] = Wih[g * 80 + f];
    float bias = bih[g] + bhh[g];
    __syncthreads();

    int tmax = min(128, T_LEN - t0);
    const size_t st = (size_t)BATCH * G4;

    for (int i8 = 0; i8 < tmax / 8; i8++) {
        u64 a0 = pk(bias, bias), a1 = a0, a2 = a0, a3 = a0;
#pragma unroll
        for (int f = 0; f < 80; f++) {
            u64 pA, pB, pC, pD;
            uint32_t sa = (uint32_t)__cvta_generic_to_shared(&xs2[f][i8 * 4]);
            asm("ld.shared.v2.u64 {%0, %1}, [%2];"    : "=l"(pA), "=l"(pB) : "r"(sa));
            asm("ld.shared.v2.u64 {%0, %1}, [%2+16];" : "=l"(pC), "=l"(pD) : "r"(sa));
            u64 w2 = pk(w[f], w[f]);
            fma2(a0, w2, pA); fma2(a1, w2, pB);
            fma2(a2, w2, pC); fma2(a3, w2, pD);
        }
        size_t o = ((size_t)(t0 + i8 * 8) * BATCH + b) * G4 + g;
        float lo, hi;
        upk(a0, lo, hi); xi[o]          = lo; xi[o + st]     = hi;
        upk(a1, lo, hi); xi[o + 2 * st] = lo; xi[o + 3 * st] = hi;
        upk(a2, lo, hi); xi[o + 4 * st] = lo; xi[o + 5 * st] = hi;
        upk(a3, lo, hi); xi[o + 6 * st] = lo; xi[o + 7 * st] = hi;
    }
}

// ---------------- LSTM cell macro-body (shared by C0 / C1) ----------------
// thread u owns cell u. whh in regs, whr in regs. One __syncthreads per step.
// Returns new h[l] (same value in every warp's lane l).
template<bool EMIT_H0, bool EMIT_OUT>
__device__ __forceinline__ void cell_phase(
    int b, const float* __restrict__ xsrc, const int* __restrict__ wm_in,
    int* __restrict__ wm_out, const float* __restrict__ Whh,
    const float* __restrict__ Whr, const float* __restrict__ W2,
    const float* __restrict__ b2, float* __restrict__ h0out,
    float* __restrict__ out)
{
    const int u = threadIdx.x;
    const int w = u >> 5, l = u & 31;

    __shared__ __align__(16) float ots[128];
    __shared__ __align__(16) float hp[2][4][32];
    __shared__ __align__(16) float hbw[4][32];

    u64 whh[4][16];
#pragma unroll
    for (int q = 0; q < 4; q++) {
        const u64* p = reinterpret_cast<const u64*>(Whh + (q * HID + u) * PROJ);
#pragma unroll
        for (int j = 0; j < 16; j++) whh[q][j] = p[j];
    }
    u64 whr[16];
    {
        const u64* wr = reinterpret_cast<const u64*>(Whr + l * HID + w * 32);
#pragma unroll
        for (int j = 0; j < 16; j++) whr[j] = wr[j];
    }
    float w2v = 0.f, b2v = 0.f;
    if (EMIT_OUT) { w2v = W2[l]; b2v = b2[0]; }

    hbw[w][l] = 0.f;
    float c = 0.f;
    __syncthreads();

    const size_t strideT = (size_t)BATCH * G4;
    const float* xp = xsrc + (size_t)b * G4 + u;

    int wmv = 0;
    if (wm_in) { while ((wmv = wm_load(wm_in)) < 8) __nanosleep(200); }

    float buf[4][4];
#pragma unroll
    for (int k = 0; k < 4; k++) {
        const float* xn = xp + (size_t)k * strideT;
#pragma unroll
        for (int q = 0; q < 4; q++) buf[k][q] = __ldcs(xn + q * HID);
    }

    for (int t4 = 0; t4 < T_LEN / 4; t4++) {
        if (wm_in && t4) {
            int need = t4 * 4 + 8; if (need > T_LEN) need = T_LEN;
            while (wmv < need) { wmv = wm_load(wm_in); if (wmv < need) __nanosleep(100); }
        }
#pragma unroll
        for (int k = 0; k < 4; k++) {
            const int t = t4 * 4 + k;
            float g0 = buf[k][0], g1 = buf[k][1], g2 = buf[k][2], g3 = buf[k][3];
            if (t + 4 < T_LEN) {
                const float* xn = xp + (size_t)(t + 4) * strideT;
#pragma unroll
                for (int q = 0; q < 4; q++) buf[k][q] = __ldcs(xn + q * HID);
            }
            const u64* h2 = reinterpret_cast<const u64*>(hbw[w]);
            u64 aA0 = pk(0.f,0.f), aA1 = aA0, aA2 = aA0, aA3 = aA0;
            u64 aB0 = aA0, aB1 = aA0, aB2 = aA0, aB3 = aA0;
#pragma unroll
            for (int j = 0; j < 8; j++) {
                u64 hv = h2[j];
                fma2(aA0, whh[0][j], hv); fma2(aA1, whh[1][j], hv);
                fma2(aA2, whh[2][j], hv); fma2(aA3, whh[3][j], hv);
            }
#pragma unroll
            for (int j = 8; j < 16; j++) {
                u64 hv = h2[j];
                fma2(aB0, whh[0][j], hv); fma2(aB1, whh[1][j], hv);
                fma2(aB2, whh[2][j], hv); fma2(aB3, whh[3][j], hv);
            }
            g0 += hsum(add2(aA0, aB0));
            g1 += hsum(add2(aA1, aB1));
            g2 += hsum(add2(aA2, aB2));
            g3 += hsum(add2(aA3, aB3));

            float iv = sigm(g0), fv = sigm(g1);
            float gv = tanh_hw(g2), ov = sigm(g3);
            c = fmaf(fv, c, iv * gv);
            float ot = ov * tanh_hw(c);

            ots[u] = ot;
            __syncwarp();
            const u64* o2 = reinterpret_cast<const u64*>(ots) + w * 16;
            u64 pA = pk(0.f,0.f), pB = pA;
#pragma unroll
            for (int j = 0; j < 8; j++)  fma2(pA, whr[j], o2[j]);
#pragma unroll
            for (int j = 8; j < 16; j++) fma2(pB, whr[j], o2[j]);
            hp[k & 1][w][l] = hsum(add2(pA, pB));
            __syncthreads();
            const float (*hpv)[32] = hp[k & 1];
            float hv = (hpv[0][l] + hpv[1][l]) + (hpv[2][l] + hpv[3][l]);
            hbw[w][l] = hv;
            if (EMIT_H0) {
                if (w == 0) h0out[((size_t)t * BATCH + b) * PROJ + l] = hv;
            }
            if (EMIT_OUT) {
                if (w == 0) {
                    float val = fmaxf(hv, 0.f) * w2v;
#pragma unroll
                    for (int off = 16; off; off >>= 1)
                        val += __shfl_down_sync(0xffffffffu, val, off);
                    if (l == 0) {
                        float z = fmaxf(val + b2v, 0.f);
                        out[(size_t)b * T_LEN + t] = sigm_acc(z);
                    }
                }
            }
            __syncwarp();
        }
        if (EMIT_H0) {
            if (w == 0) {
                __threadfence();
                __syncwarp();
                if (l == 0) wm_store(wm_out, t4 * 4 + 4);
            }
        }
    }
}

// ---------------- 3-stage pipelined scan over 192 blocks ----------------
__global__ void __launch_bounds__(128, 1) scan3(
    const float* __restrict__ Whh0, const float* __restrict__ Whr0,
    const float* __restrict__ Wih1,
    const float* __restrict__ bih1, const float* __restrict__ bhh1,
    const float* __restrict__ Whh1, const float* __restrict__ Whr1,
    const float* __restrict__ W2,   const float* __restrict__ b2,
    float* __restrict__ out)
{
    const int role = blockIdx.x >> 6;      // 0: C0, 1: G, 2: C1
    const int b    = blockIdx.x & 63;
    const int u    = threadIdx.x;

    if (role == 0) {
        cell_phase<true, false>(b, g_xi, nullptr, g_wm0 + b,
                                Whh0, Whr0, nullptr, nullptr, g_h0, nullptr);
    } else if (role == 1) {
        // ---- G: xi1 gemv, 4-step windows ----
        __shared__ __align__(16) float h0win[4][32];

        u64 wih[4][16];
        float biasq[4];
#pragma unroll
        for (int q = 0; q < 4; q++) {
            const u64* p = reinterpret_cast<const u64*>(Wih1 + (q * HID + u) * PROJ);
#pragma unroll
            for (int j = 0; j < 16; j++) wih[q][j] = p[j];
            biasq[q] = bih1[q * HID + u] + bhh1[q * HID + u];
        }

        int wmv = 0;
        for (int t4 = 0; t4 < T_LEN / 4; t4++) {
            const int need = t4 * 4 + 4;
            while (wmv < need) { wmv = wm_load(&g_wm0[b]); if (wmv < need) __nanosleep(100); }
            // load h0 window: thread u -> (t = t4*4 + u/32, j = u%32)
            h0win[u >> 5][u & 31] =
                g_h0[((size_t)(t4 * 4 + (u >> 5)) * BATCH + b) * PROJ + (u & 31)];
            __syncthreads();
#pragma unroll
            for (int k = 0; k < 4; k++) {
                const u64* h2 = reinterpret_cast<const u64*>(h0win[k]);
                u64 aA0 = pk(0.f,0.f), aA1 = aA0, aA2 = aA0, aA3 = aA0;
                u64 aB0 = aA0, aB1 = aA0, aB2 = aA0, aB3 = aA0;
#pragma unroll
                for (int j = 0; j < 8; j++) {
                    u64 hv = h2[j];
                    fma2(aA0, wih[0][j], hv); fma2(aA1, wih[1][j], hv);
                    fma2(aA2, wih[2][j], hv); fma2(aA3, wih[3][j], hv);
                }
#pragma unroll
                for (int j = 8; j < 16; j++) {
                    u64 hv = h2[j];
                    fma2(aB0, wih[0][j], hv); fma2(aB1, wih[1][j], hv);
                    fma2(aB2, wih[2][j], hv); fma2(aB3, wih[3][j], hv);
                }
                float* xo = g_xi1 + ((size_t)(t4 * 4 + k) * BATCH + b) * G4;
                xo[u]           = biasq[0] + hsum(add2(aA0, aB0));
                xo[HID + u]     = biasq[1] + hsum(add2(aA1, aB1));
                xo[2*HID + u]   = biasq[2] + hsum(add2(aA2, aB2));
                xo[3*HID + u]   = biasq[3] + hsum(add2(aA3, aB3));
            }
            __threadfence();
            __syncthreads();
            if (u == 0) wm_store(&g_wm1[b], t4 * 4 + 4);
        }
    } else {
        cell_phase<false, true>(b, g_xi1, g_wm1 + b, nullptr,
                                Whh1, Whr1, W2, b2, nullptr, out);
    }
}

// ---------------- launch ----------------
extern "C" void kernel_launch(void* const* d_in, const int* in_sizes, int n_in,
                              void* d_out, int out_size)
{
    const float* x    = (const float*)d_in[0];
    const float* Wih0 = (const float*)d_in[1];
    const float* Whh0 = (const float*)d_in[2];
    const float* bih0 = (const float*)d_in[3];
    const float* bhh0 = (const float*)d_in[4];
    const float* Whr0 = (const float*)d_in[5];
    const float* Wih1 = (const float*)d_in[6];
    const float* Whh1 = (const float*)d_in[7];
    const float* bih1 = (const float*)d_in[8];
    const float* bhh1 = (const float*)d_in[9];
    const float* Whr1 = (const float*)d_in[10];
    const float* W2   = (const float*)d_in[11];
    const float* b2   = (const float*)d_in[12];
    float* out = (float*)d_out;

    float* xi;
    cudaGetSymbolAddress((void**)&xi, g_xi);

    dim3 gridG((T_LEN + 127) / 128, BATCH);

    init_wm<<<1, 64>>>();
    gemm_xi0<<<gridG, 512>>>(x, Wih0, bih0, bhh0, xi);
    scan3<<<192, 128>>>(Whh0, Whr0,
                        Wih1, bih1, bhh1, Whh1, Whr1,
                        W2, b2, out);
}